// round 14
// baseline (speedup 1.0000x reference)
#include <cuda_runtime.h>
#include <cuda_bf16.h>
#include <cstdint>

// Problem constants
#define BSZ   128
#define CDIM  2048
#define HW    196          // 14*14
#define NDESC 32
#define NANS  1845
#define CD4   (CDIM / 4)   // 512 float4 per attended row

#define TSAMP 8            // samples per chunk: one W pass for count<=8
#define TA    4            // answers per warp
#define APB   32           // answers per block
#define NST   16           // K stages (16 x 32 float4 = 512 f4 = 2048 ch)
#define DEPTH 4            // cp.async ring depth per warp

typedef unsigned long long ull;

// Scratch (no allocations allowed)
__device__ float g_att[BSZ * CDIM];      // attended [B, C]
__device__ int   g_cnt[NDESC];           // samples per descriptor
__device__ int   g_list[NDESC * BSZ];    // sample ids per descriptor

// ---------------------------------------------------------------------------
// helpers
// ---------------------------------------------------------------------------
__device__ __forceinline__ void cp_async16(uint32_t dst_smem, const void* src) {
    asm volatile("cp.async.cg.shared.global [%0], [%1], 16;"
                 :: "r"(dst_smem), "l"(src));
}
__device__ __forceinline__ void cp_commit() {
    asm volatile("cp.async.commit_group;");
}
template<int N>
__device__ __forceinline__ void cp_wait() {
    asm volatile("cp.async.wait_group %0;" :: "n"(N));
}
__device__ __forceinline__ void cp_wait_n(int n) {   // compile-time after unroll
    if (n >= 3)      cp_wait<3>();
    else if (n == 2) cp_wait<2>();
    else if (n == 1) cp_wait<1>();
    else             cp_wait<0>();
}
__device__ __forceinline__ ull fma2(ull a, ull b, ull c) {
    ull r;
    asm("fma.rn.f32x2 %0, %1, %2, %3;" : "=l"(r) : "l"(a), "l"(b), "l"(c));
    return r;
}
__device__ __forceinline__ ull add2(ull a, ull b) {
    ull r;
    asm("add.rn.f32x2 %0, %1, %2;" : "=l"(r) : "l"(a), "l"(b));
    return r;
}

// ---------------------------------------------------------------------------
// Kernel A: attended[b,c] = (1/196) * sum_hw mask[b,hw] * feat[b,c,hw]
// grid (32, 128), block 256. Block (0,0) also builds grouping tables.
// ---------------------------------------------------------------------------
__global__ void __launch_bounds__(256)
attend_kernel(const float* __restrict__ mask,
              const float* __restrict__ feat,
              const int* __restrict__ inst32) {
    __shared__ float4 smask[49];
    const int b   = blockIdx.y;
    const int tid = threadIdx.x;

    const float4* mrow = reinterpret_cast<const float4*>(mask + (size_t)b * HW);
    if (tid < 49) smask[tid] = mrow[tid];
    __syncthreads();

    const int warp = tid >> 5;
    const int lane = tid & 31;

    #pragma unroll
    for (int it = 0; it < 2; ++it) {
        const int c0 = blockIdx.x * 64 + it * 32 + warp * 4;   // 4-aligned
        const float4* fr[4];
        #pragma unroll
        for (int j = 0; j < 4; ++j)
            fr[j] = reinterpret_cast<const float4*>(
                        feat + ((size_t)b * CDIM + c0 + j) * HW);

        float4 fa[4], fb[4];
        #pragma unroll
        for (int j = 0; j < 4; ++j) fa[j] = fr[j][lane];
        if (lane < 17) {
            #pragma unroll
            for (int j = 0; j < 4; ++j) fb[j] = fr[j][lane + 32];
        }

        float s[4];
        float4 ma = smask[lane];
        #pragma unroll
        for (int j = 0; j < 4; ++j)
            s[j] = fa[j].x * ma.x + fa[j].y * ma.y + fa[j].z * ma.z + fa[j].w * ma.w;
        if (lane < 17) {
            float4 mb = smask[lane + 32];
            #pragma unroll
            for (int j = 0; j < 4; ++j)
                s[j] += fb[j].x * mb.x + fb[j].y * mb.y + fb[j].z * mb.z + fb[j].w * mb.w;
        }
        #pragma unroll
        for (int j = 0; j < 4; ++j)
            #pragma unroll
            for (int off = 16; off > 0; off >>= 1)
                s[j] += __shfl_xor_sync(0xffffffffu, s[j], off);

        if (lane == 0) {
            float4 o = make_float4(s[0] * (1.0f / HW), s[1] * (1.0f / HW),
                                   s[2] * (1.0f / HW), s[3] * (1.0f / HW));
            reinterpret_cast<float4*>(g_att)[((size_t)b * CDIM + c0) >> 2] = o;
        }
    }

    if (blockIdx.x == 0 && blockIdx.y == 0) {
        __shared__ int sh_inst[BSZ];
        __shared__ int sh_flag;
        if (tid == 0) sh_flag = 0;
        __syncthreads();
        if (tid < 64) {
            // int64 little-endian => odd 32-bit words of first 64 entries are 0
            if (inst32[2 * tid + 1] != 0) atomicOr(&sh_flag, 1);
        }
        __syncthreads();
        const bool is64 = (sh_flag == 0);
        if (tid < BSZ) sh_inst[tid] = is64 ? inst32[2 * tid] : inst32[tid];
        __syncthreads();
        if (tid == 0) {
            int cnt[NDESC];
            #pragma unroll
            for (int dd = 0; dd < NDESC; ++dd) cnt[dd] = 0;
            for (int bb = 0; bb < BSZ; ++bb) {
                int dd = sh_inst[bb];
                g_list[dd * BSZ + cnt[dd]++] = bb;
            }
            #pragma unroll
            for (int dd = 0; dd < NDESC; ++dd) g_cnt[dd] = cnt[dd];
        }
    }
}

// ---------------------------------------------------------------------------
// Kernel B: grouped GEMM — warp-private cp.async rings.
// 256 threads = 8 warps, 1 block/SM (128KB smem). Each warp owns TA=4 answer
// rows and streams its W slice through a private 4-stage x 2KB cp.async ring
// — NO block barriers inside the K loop; warps free-run on wait_group +
// syncwarp. TS=8 single W pass; f32x2 math keeps FMA issue under DRAM need.
// preds[s,a] = sum_c att[s,c] * W[d,a,c] + bias[d,a].  grid (58, 32).
// ---------------------------------------------------------------------------
__global__ void __launch_bounds__(256, 1)
gemm_kernel(const float* __restrict__ Wm,
            const float* __restrict__ bias,
            float* __restrict__ out) {
    const int d     = blockIdx.y;
    const int count = g_cnt[d];
    if (count == 0) return;

    extern __shared__ float4 dynsmem[];
    float4* Wring = dynsmem;             // [8 warps][DEPTH][TA][32 f4] = 64 KB
    float4* Att   = dynsmem + 4096;      // [TSAMP][CD4] f4 = 64 KB
    __shared__ int s_b[TSAMP];

    const int tid  = threadIdx.x;
    const int warp = tid >> 5;
    const int lane = tid & 31;

    const int aw = blockIdx.x * APB + warp * TA;
    const float4* __restrict__ W4 = reinterpret_cast<const float4*>(Wm);
    unsigned wrow[TA];
    #pragma unroll
    for (int ta = 0; ta < TA; ++ta) {
        int a = aw + ta; if (a >= NANS) a = NANS - 1;   // clamp; stores guarded
        wrow[ta] = (unsigned)((d * NANS + a) * CD4);
    }
    const float4* __restrict__ gatt4 = reinterpret_cast<const float4*>(g_att);

    // this warp's ring (float4 units and smem byte address)
    float4* ring = Wring + warp * (DEPTH * TA * 32);
    const uint32_t ring_b = (uint32_t)__cvta_generic_to_shared(ring);

    const int nchunks = (count + TSAMP - 1) / TSAMP;   // ==1 for ~98% of d

    for (int sc = 0; sc < nchunks; ++sc) {
        if (tid < TSAMP) {
            int si = sc * TSAMP + tid;
            s_b[tid] = (si < count) ? g_list[d * BSZ + si] : -1;
        }
        __syncthreads();
        // stage attended tile (full K), zeros for padding samples (L2 hits)
        #pragma unroll
        for (int r = 0; r < 16; ++r) {             // 4096 f4 / 256 thr
            int i  = r * 256 + tid;
            int ts = i >> 9;
            int cc = i & (CD4 - 1);
            int bb = s_b[ts];
            float4 v = make_float4(0.f, 0.f, 0.f, 0.f);
            if (bb >= 0) v = gatt4[(size_t)bb * CD4 + cc];
            Att[i] = v;
        }
        __syncthreads();

        // ---- prime the private ring: stages 0..3, one commit group each ----
        #pragma unroll
        for (int ps = 0; ps < DEPTH; ++ps) {
            uint32_t dst = ring_b + (unsigned)(ps * 2048 + lane * 16);
            #pragma unroll
            for (int ta = 0; ta < TA; ++ta)
                cp_async16(dst + (unsigned)(ta * 512),
                           W4 + wrow[ta] + (unsigned)(ps * 32 + lane));
            cp_commit();
        }

        ull acc[TA][TSAMP];
        #pragma unroll
        for (int ta = 0; ta < TA; ++ta)
            #pragma unroll
            for (int j = 0; j < TSAMP; ++j) acc[ta][j] = 0ull;

        #pragma unroll
        for (int s = 0; s < NST; ++s) {
            cp_wait_n(15 - s < 3 ? 15 - s : 3);    // stage s landed
            __syncwarp();

            // read this stage: 4 rows x column 'lane' (ulonglong2 = f4)
            const float4* wst = ring + (s & (DEPTH - 1)) * (TA * 32) + lane;
            ulonglong2 w[TA];
            #pragma unroll
            for (int ta = 0; ta < TA; ++ta)
                w[ta] = *reinterpret_cast<const ulonglong2*>(wst + ta * 32);

            const int scol = s * 32 + lane;        // global f4 column
            #pragma unroll
            for (int j = 0; j < TSAMP; ++j) {
                ulonglong2 av = *reinterpret_cast<const ulonglong2*>(
                                    Att + (j << 9) + scol);
                #pragma unroll
                for (int ta = 0; ta < TA; ++ta) {
                    acc[ta][j] = fma2(w[ta].x, av.x, acc[ta][j]);
                    acc[ta][j] = fma2(w[ta].y, av.y, acc[ta][j]);
                }
            }
            __syncwarp();                           // stage consumed

            if (s + DEPTH < NST) {                 // refill ring slot
                uint32_t dst = ring_b +
                    (unsigned)(((s + DEPTH) & (DEPTH - 1)) * 2048 + lane * 16);
                #pragma unroll
                for (int ta = 0; ta < TA; ++ta)
                    cp_async16(dst + (unsigned)(ta * 512),
                               W4 + wrow[ta] + (unsigned)((s + DEPTH) * 32 + lane));
                cp_commit();
            }
        }

        // butterfly reduce packed accs across the warp
        #pragma unroll
        for (int ta = 0; ta < TA; ++ta)
            #pragma unroll
            for (int j = 0; j < TSAMP; ++j)
                #pragma unroll
                for (int off = 16; off > 0; off >>= 1)
                    acc[ta][j] = add2(acc[ta][j],
                        __shfl_xor_sync(0xffffffffu, acc[ta][j], off));

        // 32 lanes = 4 answers x 8 samples: lane = ta*8 + j
        {
            int ta = lane >> 3;
            int j  = lane & 7;
            int a  = aw + ta;
            int bb = s_b[j];
            if (a < NANS && bb >= 0) {
                ull v = acc[ta][j];
                float lo = __uint_as_float((unsigned)(v & 0xffffffffull));
                float hi = __uint_as_float((unsigned)(v >> 32));
                out[(size_t)bb * NANS + a] = lo + hi + bias[(size_t)d * NANS + a];
            }
        }
        __syncthreads();   // protect s_b / Att before next chunk rewrites
    }
}

// ---------------------------------------------------------------------------
extern "C" void kernel_launch(void* const* d_in, const int* in_sizes, int n_in,
                              void* d_out, int out_size) {
    const float* mask = (const float*)d_in[0];   // [B,1,14,14]
    const float* feat = (const float*)d_in[1];   // [B,C,14,14]
    const int*   inst = (const int*)d_in[2];     // [B] int64 or int32
    const float* Wm   = (const float*)d_in[3];   // [32,1845,2048]
    const float* bias = (const float*)d_in[4];   // [32,1845]
    float* out = (float*)d_out;                  // [B,1845]

    static const size_t GEMM_SMEM = 8192 * sizeof(float4);   // 128 KB
    cudaFuncSetAttribute(gemm_kernel,
                         cudaFuncAttributeMaxDynamicSharedMemorySize,
                         (int)GEMM_SMEM);

    attend_kernel<<<dim3(32, 128), 256>>>(mask, feat, inst);
    gemm_kernel<<<dim3((NANS + APB - 1) / APB, NDESC), 256, GEMM_SMEM>>>(Wm, bias, out);
}